// round 12
// baseline (speedup 1.0000x reference)
#include <cuda_runtime.h>
#include <cstdint>

#define NN 50000
#define NE 1600000
#define DD 64
#define RR 4
#define LL 4
#define NB 256
#define NEG_SLOPE 0.2f
#define XK (RR * DD + DD)          // 320: fused input dim per node

// ---------------- device scratch (static, allocation-free, 16B-aligned) ----------------
__device__ __align__(16) float    g_hbuf0[NN * DD];
__device__ __align__(16) float    g_hbuf1[NN * DD];
__device__ __align__(16) float    g_sum[NN * RR * DD];   // per-(node,rel) edge sums, 51.2MB
__device__ __align__(16) float    g_z[NN * DD];          // GAT z
__device__ __align__(16) float    g_el[NN];
__device__ __align__(16) float    g_er[NN];
__device__ __align__(16) unsigned g_menc[NN];            // order-preserving float-max enc
__device__ __align__(16) float    g_den[NN];
__device__ __align__(16) float    g_ex[NE];
__device__ __align__(16) float    g_hg[NN * DD];

// ---------------- helpers ----------------
__device__ __forceinline__ const float* layer_in(int l, const float* h0) {
    if (l == 0) return h0;
    return ((l - 1) & 1) ? g_hbuf1 : g_hbuf0;
}
__device__ __forceinline__ float* layer_out(int l) {
    return (l & 1) ? g_hbuf1 : g_hbuf0;
}
__device__ __forceinline__ unsigned fenc(float f) {
    unsigned u = __float_as_uint(f);
    return (u & 0x80000000u) ? ~u : (u | 0x80000000u);
}
__device__ __forceinline__ float fdec(unsigned k) {
    return (k & 0x80000000u) ? __uint_as_float(k & 0x7FFFFFFFu)
                             : __uint_as_float(~k);
}
__device__ __forceinline__ void red_add_v4(float* addr, float x, float y, float z, float w) {
    asm volatile("red.global.add.v4.f32 [%0], {%1,%2,%3,%4};"
                 :: "l"(addr), "f"(x), "f"(y), "f"(z), "f"(w) : "memory");
}
__device__ __forceinline__ unsigned long long pack2(float v) {
    unsigned long long p;
    asm("mov.b64 %0, {%1,%1};" : "=l"(p) : "f"(v));
    return p;
}
__device__ __forceinline__ void fma2(unsigned long long& acc, unsigned long long a,
                                     unsigned long long b) {
    asm("fma.rn.f32x2 %0, %1, %2, %0;" : "+l"(acc) : "l"(a), "l"(b));
}
__device__ __forceinline__ void unpack2(unsigned long long p, float& lo, float& hi) {
    asm("mov.b64 {%0,%1}, %2;" : "=f"(lo), "=f"(hi) : "l"(p));
}

// ---------------- zero g_sum (before layer 0) ----------------
__global__ void k_zero_sum() {
    int i = blockIdx.x * blockDim.x + threadIdx.x;
    float4 z4 = make_float4(0.f, 0.f, 0.f, 0.f);
    if (i < NN * RR * DD / 4) ((float4*)g_sum)[i] = z4;
}

// ---------------- edge gather: g_sum[dst, etype] += h[src] ----------------
__global__ void __launch_bounds__(256) k_edge_gather(const int* __restrict__ src,
                                                     const int* __restrict__ dst,
                                                     const int* __restrict__ et,
                                                     const float* __restrict__ h0, int l) {
    const float* h = layer_in(l, h0);
    int t = blockIdx.x * 256 + threadIdx.x;
    int e = t >> 4;
    if (e >= NE) return;
    int k = t & 15;
    int s = __ldg(src + e), d = __ldg(dst + e), r = __ldg(et + e);
    const float4 v = *(const float4*)(h + (size_t)s * DD + k * 4);
    red_add_v4(g_sum + (size_t)d * (RR * DD) + r * DD + k * 4, v.x, v.y, v.z, v.w);
}

// ---------------- fused node update:  h' = relu([g_sum | h] @ [Wrel;Wloop] + b) ----------------
// 256 threads = 128 nodes x 2 halves; f32x2 packed FMA; W (80KB) + x chunks in smem.
__global__ void __launch_bounds__(256) k_nodeF(const float* __restrict__ h0, int l,
                                               const float* __restrict__ Wrel_l,
                                               const float* __restrict__ Wloop_l,
                                               const float* __restrict__ br) {
    extern __shared__ float sm[];
    float* Ws = sm;                    // XK*DD = 20480 floats
    float* Bs = Ws + XK * DD;          // 64
    float* Xs = Bs + DD;               // 128*33 = 4224
    const float* h = layer_in(l, h0);
    float* hout = layer_out(l);
    int tid = threadIdx.x;
    int base = blockIdx.x * 128;

    {   // stage weights (float4)
        float4* Ws4 = (float4*)Ws;
        const float4* A4 = (const float4*)Wrel_l;
        for (int i = tid; i < RR * DD * DD / 4; i += 256) Ws4[i] = A4[i];
        const float4* B4 = (const float4*)Wloop_l;
        for (int i = tid; i < DD * DD / 4; i += 256) Ws4[RR * DD * DD / 4 + i] = B4[i];
        if (tid < DD) Bs[tid] = br[tid];
    }

    int nl = tid >> 1;         // block-local node 0..127
    int hf = tid & 1;          // output half
    int node = base + nl;

    unsigned long long acc[16];
#pragma unroll
    for (int i = 0; i < 16; i++) acc[i] = 0ull;

    for (int c = 0; c < 10; c++) {
        __syncthreads();
        // stage x chunk: 128 nodes x 32 inputs (c<8: g_sum, else h)
        int f = tid;
#pragma unroll
        for (int i = 0; i < 16; i++, f += 256) {
            int row = f >> 5, col = f & 31;
            int n = base + row;
            float v = 0.f;
            if (n < NN) {
                if (c < 8) v = g_sum[(size_t)n * (RR * DD) + c * 32 + col];
                else       v = h[(size_t)n * DD + (c - 8) * 32 + col];
            }
            Xs[row * 33 + col] = v;
        }
        __syncthreads();
        const float* wbase = Ws + (c * 32) * DD + hf * 32;
#pragma unroll 8
        for (int j = 0; j < 32; j++) {
            unsigned long long xp = pack2(Xs[nl * 33 + j]);
            const float* wr = wbase + j * DD;
#pragma unroll
            for (int q = 0; q < 8; q++) {
                ulonglong2 w = *(const ulonglong2*)(wr + 4 * q);
                fma2(acc[2 * q],     xp, w.x);
                fma2(acc[2 * q + 1], xp, w.y);
            }
        }
    }

    if (node < NN) {
        float o[32];
#pragma unroll
        for (int i = 0; i < 16; i++) {
            float lo, hi;
            unpack2(acc[i], lo, hi);
            o[2 * i]     = fmaxf(lo + Bs[hf * 32 + 2 * i], 0.f);
            o[2 * i + 1] = fmaxf(hi + Bs[hf * 32 + 2 * i + 1], 0.f);
        }
        float4* op = (float4*)(hout + (size_t)node * DD + hf * 32);
#pragma unroll
        for (int q = 0; q < 8; q++)
            op[q] = make_float4(o[4 * q], o[4 * q + 1], o[4 * q + 2], o[4 * q + 3]);
    }

    // zero this block's g_sum rows for the next layer (all staging reads are done:
    // every thread passed chunk-8's barrier before reaching here)
    __syncthreads();
    int nodes_blk = NN - base; if (nodes_blk > 128) nodes_blk = 128;
    int limit = nodes_blk * (RR * DD) / 4;
    float4* zp = (float4*)(g_sum + (size_t)base * (RR * DD));
    float4 z4 = make_float4(0.f, 0.f, 0.f, 0.f);
    for (int f2 = tid; f2 < limit; f2 += 256) zp[f2] = z4;
}

// ---------------- GAT: z = h@Wg, el/er dots; init hg/menc/den ----------------
__global__ void __launch_bounds__(256) k_gatz(const float* __restrict__ h0,
                                              const float* __restrict__ Wg,
                                              const float* __restrict__ al,
                                              const float* __restrict__ ar) {
    extern __shared__ float sm[];
    float* Ws = sm;                 // 4096
    float* Aa = Ws + DD * DD;       // 64
    float* Ab = Aa + DD;            // 64
    float* Xs = Ab + DD;            // 128*33
    const float* h = layer_in(LL, h0);
    int tid = threadIdx.x;
    int base = blockIdx.x * 128;

    {
        float4* Ws4 = (float4*)Ws;
        const float4* A4 = (const float4*)Wg;
        for (int i = tid; i < DD * DD / 4; i += 256) Ws4[i] = A4[i];
        if (tid < DD) Aa[tid] = al[tid];
        else if (tid < 2 * DD) Ab[tid - DD] = ar[tid - DD];
    }

    int nl = tid >> 1;
    int hf = tid & 1;
    int node = base + nl;

    unsigned long long acc[16];
#pragma unroll
    for (int i = 0; i < 16; i++) acc[i] = 0ull;

    for (int c = 0; c < 2; c++) {
        __syncthreads();
        int f = tid;
#pragma unroll
        for (int i = 0; i < 16; i++, f += 256) {
            int row = f >> 5, col = f & 31;
            int n = base + row;
            Xs[row * 33 + col] = (n < NN) ? h[(size_t)n * DD + c * 32 + col] : 0.f;
        }
        __syncthreads();
        const float* wbase = Ws + (c * 32) * DD + hf * 32;
#pragma unroll 8
        for (int j = 0; j < 32; j++) {
            unsigned long long xp = pack2(Xs[nl * 33 + j]);
            const float* wr = wbase + j * DD;
#pragma unroll
            for (int q = 0; q < 8; q++) {
                ulonglong2 w = *(const ulonglong2*)(wr + 4 * q);
                fma2(acc[2 * q],     xp, w.x);
                fma2(acc[2 * q + 1], xp, w.y);
            }
        }
    }

    float z[32];
    float el_p = 0.f, er_p = 0.f;
#pragma unroll
    for (int i = 0; i < 16; i++) {
        float lo, hi;
        unpack2(acc[i], lo, hi);
        z[2 * i] = lo; z[2 * i + 1] = hi;
    }
#pragma unroll
    for (int i = 0; i < 32; i++) {
        el_p = fmaf(z[i], Aa[hf * 32 + i], el_p);
        er_p = fmaf(z[i], Ab[hf * 32 + i], er_p);
    }
    // combine halves (lanes tid, tid^1 are the same node) — all lanes participate
    float el_v = el_p + __shfl_xor_sync(0xffffffffu, el_p, 1);
    float er_v = er_p + __shfl_xor_sync(0xffffffffu, er_p, 1);

    if (node < NN) {
        float4* zp = (float4*)(g_z + (size_t)node * DD + hf * 32);
        float4* hz = (float4*)(g_hg + (size_t)node * DD + hf * 32);
        float4 z4 = make_float4(0.f, 0.f, 0.f, 0.f);
#pragma unroll
        for (int q = 0; q < 8; q++) {
            zp[q] = make_float4(z[4 * q], z[4 * q + 1], z[4 * q + 2], z[4 * q + 3]);
            hz[q] = z4;
        }
        if (hf == 0) {
            g_el[node] = el_v;
            g_er[node] = er_v;
            g_menc[node] = 0x007FFFFFu;    // enc(-inf)
            g_den[node] = 0.f;
        }
    }
}

// ---------------- GAT edge passes ----------------
__device__ __forceinline__ float edge_e(const int* src, const int* dst, int e,
                                        int& s, int& d) {
    s = __ldg(src + e); d = __ldg(dst + e);
    float ev = g_el[s] + g_er[d];
    return ev > 0.f ? ev : NEG_SLOPE * ev;
}

__global__ void __launch_bounds__(256) k_edge_max(const int* __restrict__ src,
                                                   const int* __restrict__ dst) {
    int e = blockIdx.x * 256 + threadIdx.x;
    if (e >= NE) return;
    int s, d;
    float ev = edge_e(src, dst, e, s, d);
    atomicMax(&g_menc[d], fenc(ev));
}

__global__ void __launch_bounds__(256) k_edge_exp(const int* __restrict__ src,
                                                   const int* __restrict__ dst) {
    int e = blockIdx.x * 256 + threadIdx.x;
    if (e >= NE) return;
    int s, d;
    float ev = edge_e(src, dst, e, s, d);
    float m = fdec(g_menc[d]);
    float ex = __expf(ev - m);
    g_ex[e] = ex;
    atomicAdd(&g_den[d], ex);
}

__global__ void __launch_bounds__(256) k_edge_hg(const int* __restrict__ src,
                                                  const int* __restrict__ dst) {
    int t = blockIdx.x * 256 + threadIdx.x;
    int e = t >> 4;
    if (e >= NE) return;
    int k = t & 15;
    int s = __ldg(src + e), d = __ldg(dst + e);
    float w = __fdividef(__ldg(&g_ex[e]), fmaxf(__ldg(&g_den[d]), 1e-9f));
    const float4 z = *(const float4*)(g_z + (size_t)s * DD + k * 4);
    red_add_v4(g_hg + (size_t)d * DD + k * 4, w * z.x, w * z.y, w * z.z, w * z.w);
}

// ---------------- pooling + dense head ----------------
__global__ void k_out_init(const float* __restrict__ bd, float* __restrict__ out) {
    int t = threadIdx.x;
    if (t < NB) out[t] = bd[0];
}

__global__ void __launch_bounds__(256) k_pool(const float* __restrict__ Wd,
                                              const int* __restrict__ gids,
                                              float* __restrict__ out) {
    int warp = (blockIdx.x * 256 + threadIdx.x) >> 5;
    int lane = threadIdx.x & 31;
    if (warp >= NN) return;
    float w0 = __ldg(Wd + lane), w1 = __ldg(Wd + 32 + lane);
    float p = g_hg[warp * DD + lane] * w0 + g_hg[warp * DD + 32 + lane] * w1;
    p += __shfl_xor_sync(0xffffffffu, p, 16);
    p += __shfl_xor_sync(0xffffffffu, p, 8);
    p += __shfl_xor_sync(0xffffffffu, p, 4);
    p += __shfl_xor_sync(0xffffffffu, p, 2);
    p += __shfl_xor_sync(0xffffffffu, p, 1);
    if (lane == 0) atomicAdd(out + __ldg(gids + warp), p);
}

// ---------------- launcher ----------------
extern "C" void kernel_launch(void* const* d_in, const int* in_sizes, int n_in,
                              void* d_out, int out_size) {
    const float* h    = (const float*)d_in[0];
    const float* Wrel = (const float*)d_in[1];
    const float* Wloop= (const float*)d_in[2];
    const float* brel = (const float*)d_in[3];
    const float* Wg   = (const float*)d_in[4];
    const float* al   = (const float*)d_in[5];
    const float* ar   = (const float*)d_in[6];
    const float* Wd   = (const float*)d_in[7];
    const float* bd   = (const float*)d_in[8];
    const int*   src  = (const int*)d_in[9];
    const int*   dst  = (const int*)d_in[10];
    const int*   et   = (const int*)d_in[11];
    const int*   gids = (const int*)d_in[12];
    float* out = (float*)d_out;

    const int nf_smem = (XK * DD + DD + 128 * 33) * 4;       // 99072 B
    const int gz_smem = (DD * DD + 2 * DD + 128 * 33) * 4;   // 33792 B
    cudaFuncSetAttribute((const void*)k_nodeF, cudaFuncAttributeMaxDynamicSharedMemorySize, nf_smem);
    cudaFuncSetAttribute((const void*)k_gatz,  cudaFuncAttributeMaxDynamicSharedMemorySize, gz_smem);

    const int nblkF  = (NN + 127) / 128;                 // 391
    const int zblk   = (NN * RR * DD / 4 + 255) / 256;   // 12500
    const int eblk16 = (NE * 16 + 255) / 256;            // 100000
    const int eblk   = (NE + 255) / 256;                 // 6250
    const int pblk   = (NN * 32 + 255) / 256;            // 6250

    k_zero_sum<<<zblk, 256>>>();
    for (int l = 0; l < LL; l++) {
        k_edge_gather<<<eblk16, 256>>>(src, dst, et, h, l);
        k_nodeF<<<nblkF, 256, nf_smem>>>(h, l, Wrel + l * RR * DD * DD,
                                         Wloop + l * DD * DD, brel + l * DD);
    }
    k_gatz<<<nblkF, 256, gz_smem>>>(h, Wg, al, ar);
    k_edge_max<<<eblk, 256>>>(src, dst);
    k_edge_exp<<<eblk, 256>>>(src, dst);
    k_edge_hg<<<eblk16, 256>>>(src, dst);
    k_out_init<<<1, NB>>>(bd, out);
    k_pool<<<pblk, 256>>>(Wd, gids, out);
}

// round 13
// speedup vs baseline: 1.1283x; 1.1283x over previous
#include <cuda_runtime.h>
#include <cstdint>

#define NN 50000
#define NE 1600000
#define DD 64
#define RR 4
#define LL 4
#define NB 256
#define NEG_SLOPE 0.2f
#define XK (RR * DD + DD)          // 320: fused input dim per node

// ---------------- device scratch (static, allocation-free, 16B-aligned) ----------------
__device__ __align__(16) float g_hbuf0[NN * DD];
__device__ __align__(16) float g_hbuf1[NN * DD];
__device__ __align__(16) float g_sum[NN * RR * DD];   // per-(node,rel) edge sums
__device__ __align__(16) float g_z[NN * DD];          // GAT z
__device__ __align__(16) float g_el[NN];
__device__ __align__(16) float g_er[NN];
__device__ __align__(16) int   g_deg[NN];
__device__ __align__(16) int   g_rows[NN + 1];
__device__ __align__(16) int   g_wcur[NN];
__device__ __align__(16) unsigned g_epack[NE];        // src | (rel<<16), sorted by dst

// ---------------- helpers ----------------
__device__ __forceinline__ const float* layer_in(int l, const float* h0) {
    if (l == 0) return h0;
    return ((l - 1) & 1) ? g_hbuf1 : g_hbuf0;
}
__device__ __forceinline__ float* layer_out(int l) {
    return (l & 1) ? g_hbuf1 : g_hbuf0;
}
__device__ __forceinline__ unsigned long long pack2(float v) {
    unsigned long long p;
    asm("mov.b64 %0, {%1,%1};" : "=l"(p) : "f"(v));
    return p;
}
__device__ __forceinline__ void fma2(unsigned long long& acc, unsigned long long a,
                                     unsigned long long b) {
    asm("fma.rn.f32x2 %0, %1, %2, %0;" : "+l"(acc) : "l"(a), "l"(b));
}
__device__ __forceinline__ void unpack2(unsigned long long p, float& lo, float& hi) {
    asm("mov.b64 {%0,%1}, %2;" : "=f"(lo), "=f"(hi) : "l"(p));
}

// ================= CSR build =================
__global__ void k_zero_deg() {
    int i = blockIdx.x * blockDim.x + threadIdx.x;
    if (i < NN) g_deg[i] = 0;
}
__global__ void __launch_bounds__(256) k_hist(const int* __restrict__ dst) {
    int e = blockIdx.x * 256 + threadIdx.x;
    if (e < NE) atomicAdd(&g_deg[__ldg(dst + e)], 1);
}
__global__ void __launch_bounds__(1024) k_scan() {
    __shared__ int part[1024];
    int tid = threadIdx.x;
    const int chunk = (NN + 1023) / 1024;          // 49
    int b = tid * chunk;
    int e = b + chunk; if (e > NN) e = NN;
    int s = 0;
    for (int i = b; i < e; i++) s += g_deg[i];
    part[tid] = s;
    __syncthreads();
    for (int off = 1; off < 1024; off <<= 1) {
        int v = (tid >= off) ? part[tid - off] : 0;
        __syncthreads();
        part[tid] += v;
        __syncthreads();
    }
    int run = part[tid] - s;                       // exclusive
    for (int i = b; i < e; i++) {
        g_rows[i] = run;
        g_wcur[i] = run;
        run += g_deg[i];
    }
    if (tid == 1023) g_rows[NN] = run;
}
__global__ void __launch_bounds__(256) k_place(const int* __restrict__ src,
                                               const int* __restrict__ dst,
                                               const int* __restrict__ et) {
    int e = blockIdx.x * 256 + threadIdx.x;
    if (e >= NE) return;
    int d = __ldg(dst + e);
    int pos = atomicAdd(&g_wcur[d], 1);
    g_epack[pos] = (unsigned)__ldg(src + e) | ((unsigned)__ldg(et + e) << 16);
}

// ================= CSR aggregation: g_sum[n][r] = sum h[src] over in-edges =================
// warp per node; lane owns cols {lane, lane+32}; acc[4 rels][2] in registers.
__global__ void __launch_bounds__(256) k_agg_csr(const float* __restrict__ h0, int l) {
    const float* h = layer_in(l, h0);
    int warp = (blockIdx.x * 256 + threadIdx.x) >> 5;
    int lane = threadIdx.x & 31;
    if (warp >= NN) return;
    int beg = __ldg(&g_rows[warp]), end = __ldg(&g_rows[warp + 1]);
    float a00 = 0.f, a01 = 0.f, a10 = 0.f, a11 = 0.f;
    float a20 = 0.f, a21 = 0.f, a30 = 0.f, a31 = 0.f;
    int i = beg;
    for (; i + 4 <= end; i += 4) {
        unsigned p0 = __ldg(&g_epack[i]);
        unsigned p1 = __ldg(&g_epack[i + 1]);
        unsigned p2 = __ldg(&g_epack[i + 2]);
        unsigned p3 = __ldg(&g_epack[i + 3]);
        const float* r0 = h + (size_t)(p0 & 0xffffu) * DD + lane;
        const float* r1 = h + (size_t)(p1 & 0xffffu) * DD + lane;
        const float* r2 = h + (size_t)(p2 & 0xffffu) * DD + lane;
        const float* r3 = h + (size_t)(p3 & 0xffffu) * DD + lane;
        float v00 = __ldg(r0), v01 = __ldg(r0 + 32);
        float v10 = __ldg(r1), v11 = __ldg(r1 + 32);
        float v20 = __ldg(r2), v21 = __ldg(r2 + 32);
        float v30 = __ldg(r3), v31 = __ldg(r3 + 32);
        unsigned q0 = p0 >> 16, q1 = p1 >> 16, q2 = p2 >> 16, q3 = p3 >> 16;
        if (q0 == 0) { a00 += v00; a01 += v01; } else if (q0 == 1) { a10 += v00; a11 += v01; }
        else if (q0 == 2) { a20 += v00; a21 += v01; } else { a30 += v00; a31 += v01; }
        if (q1 == 0) { a00 += v10; a01 += v11; } else if (q1 == 1) { a10 += v10; a11 += v11; }
        else if (q1 == 2) { a20 += v10; a21 += v11; } else { a30 += v10; a31 += v11; }
        if (q2 == 0) { a00 += v20; a01 += v21; } else if (q2 == 1) { a10 += v20; a11 += v21; }
        else if (q2 == 2) { a20 += v20; a21 += v21; } else { a30 += v20; a31 += v21; }
        if (q3 == 0) { a00 += v30; a01 += v31; } else if (q3 == 1) { a10 += v30; a11 += v31; }
        else if (q3 == 2) { a20 += v30; a21 += v31; } else { a30 += v30; a31 += v31; }
    }
    for (; i < end; i++) {
        unsigned p = __ldg(&g_epack[i]);
        const float* r = h + (size_t)(p & 0xffffu) * DD + lane;
        float v0 = __ldg(r), v1 = __ldg(r + 32);
        unsigned q = p >> 16;
        if (q == 0) { a00 += v0; a01 += v1; } else if (q == 1) { a10 += v0; a11 += v1; }
        else if (q == 2) { a20 += v0; a21 += v1; } else { a30 += v0; a31 += v1; }
    }
    float* o = g_sum + (size_t)warp * (RR * DD);
    o[lane] = a00;            o[lane + 32] = a01;
    o[DD + lane] = a10;       o[DD + lane + 32] = a11;
    o[2 * DD + lane] = a20;   o[2 * DD + lane + 32] = a21;
    o[3 * DD + lane] = a30;   o[3 * DD + lane + 32] = a31;
}

// ================= fused node update: h' = relu([g_sum | h] @ [Wrel;Wloop] + b) =================
__global__ void __launch_bounds__(256) k_nodeF(const float* __restrict__ h0, int l,
                                               const float* __restrict__ Wrel_l,
                                               const float* __restrict__ Wloop_l,
                                               const float* __restrict__ br) {
    extern __shared__ float sm[];
    float* Ws = sm;                    // XK*DD = 20480 floats
    float* Bs = Ws + XK * DD;          // 64
    float* Xs = Bs + DD;               // 128*33
    const float* h = layer_in(l, h0);
    float* hout = layer_out(l);
    int tid = threadIdx.x;
    int base = blockIdx.x * 128;

    {   // stage weights (float4)
        float4* Ws4 = (float4*)Ws;
        const float4* A4 = (const float4*)Wrel_l;
        for (int i = tid; i < RR * DD * DD / 4; i += 256) Ws4[i] = A4[i];
        const float4* B4 = (const float4*)Wloop_l;
        for (int i = tid; i < DD * DD / 4; i += 256) Ws4[RR * DD * DD / 4 + i] = B4[i];
        if (tid < DD) Bs[tid] = br[tid];
    }

    int nl = tid >> 1;
    int hf = tid & 1;
    int node = base + nl;

    unsigned long long acc[16];
#pragma unroll
    for (int i = 0; i < 16; i++) acc[i] = 0ull;

    for (int c = 0; c < 10; c++) {
        __syncthreads();
        int f = tid;
#pragma unroll
        for (int i = 0; i < 16; i++, f += 256) {
            int row = f >> 5, col = f & 31;
            int n = base + row;
            float v = 0.f;
            if (n < NN) {
                if (c < 8) v = g_sum[(size_t)n * (RR * DD) + c * 32 + col];
                else       v = h[(size_t)n * DD + (c - 8) * 32 + col];
            }
            Xs[row * 33 + col] = v;
        }
        __syncthreads();
        const float* wbase = Ws + (c * 32) * DD + hf * 32;
#pragma unroll 8
        for (int j = 0; j < 32; j++) {
            unsigned long long xp = pack2(Xs[nl * 33 + j]);
            const float* wr = wbase + j * DD;
#pragma unroll
            for (int q = 0; q < 8; q++) {
                ulonglong2 w = *(const ulonglong2*)(wr + 4 * q);
                fma2(acc[2 * q],     xp, w.x);
                fma2(acc[2 * q + 1], xp, w.y);
            }
        }
    }

    if (node < NN) {
        float o[32];
#pragma unroll
        for (int i = 0; i < 16; i++) {
            float lo, hi;
            unpack2(acc[i], lo, hi);
            o[2 * i]     = fmaxf(lo + Bs[hf * 32 + 2 * i], 0.f);
            o[2 * i + 1] = fmaxf(hi + Bs[hf * 32 + 2 * i + 1], 0.f);
        }
        float4* op = (float4*)(hout + (size_t)node * DD + hf * 32);
#pragma unroll
        for (int q = 0; q < 8; q++)
            op[q] = make_float4(o[4 * q], o[4 * q + 1], o[4 * q + 2], o[4 * q + 3]);
    }
}

// ================= GAT: z = h@Wg, el/er dots =================
__global__ void __launch_bounds__(256) k_gatz(const float* __restrict__ h0,
                                              const float* __restrict__ Wg,
                                              const float* __restrict__ al,
                                              const float* __restrict__ ar) {
    extern __shared__ float sm[];
    float* Ws = sm;                 // 4096
    float* Aa = Ws + DD * DD;       // 64
    float* Ab = Aa + DD;            // 64
    float* Xs = Ab + DD;            // 128*33
    const float* h = layer_in(LL, h0);
    int tid = threadIdx.x;
    int base = blockIdx.x * 128;

    {
        float4* Ws4 = (float4*)Ws;
        const float4* A4 = (const float4*)Wg;
        for (int i = tid; i < DD * DD / 4; i += 256) Ws4[i] = A4[i];
        if (tid < DD) Aa[tid] = al[tid];
        else if (tid < 2 * DD) Ab[tid - DD] = ar[tid - DD];
    }

    int nl = tid >> 1;
    int hf = tid & 1;
    int node = base + nl;

    unsigned long long acc[16];
#pragma unroll
    for (int i = 0; i < 16; i++) acc[i] = 0ull;

    for (int c = 0; c < 2; c++) {
        __syncthreads();
        int f = tid;
#pragma unroll
        for (int i = 0; i < 16; i++, f += 256) {
            int row = f >> 5, col = f & 31;
            int n = base + row;
            Xs[row * 33 + col] = (n < NN) ? h[(size_t)n * DD + c * 32 + col] : 0.f;
        }
        __syncthreads();
        const float* wbase = Ws + (c * 32) * DD + hf * 32;
#pragma unroll 8
        for (int j = 0; j < 32; j++) {
            unsigned long long xp = pack2(Xs[nl * 33 + j]);
            const float* wr = wbase + j * DD;
#pragma unroll
            for (int q = 0; q < 8; q++) {
                ulonglong2 w = *(const ulonglong2*)(wr + 4 * q);
                fma2(acc[2 * q],     xp, w.x);
                fma2(acc[2 * q + 1], xp, w.y);
            }
        }
    }

    float z[32];
    float el_p = 0.f, er_p = 0.f;
#pragma unroll
    for (int i = 0; i < 16; i++) {
        float lo, hi;
        unpack2(acc[i], lo, hi);
        z[2 * i] = lo; z[2 * i + 1] = hi;
    }
#pragma unroll
    for (int i = 0; i < 32; i++) {
        el_p = fmaf(z[i], Aa[hf * 32 + i], el_p);
        er_p = fmaf(z[i], Ab[hf * 32 + i], er_p);
    }
    float el_v = el_p + __shfl_xor_sync(0xffffffffu, el_p, 1);
    float er_v = er_p + __shfl_xor_sync(0xffffffffu, er_p, 1);

    if (node < NN) {
        float4* zp = (float4*)(g_z + (size_t)node * DD + hf * 32);
#pragma unroll
        for (int q = 0; q < 8; q++)
            zp[q] = make_float4(z[4 * q], z[4 * q + 1], z[4 * q + 2], z[4 * q + 3]);
        if (hf == 0) {
            g_el[node] = el_v;
            g_er[node] = er_v;
        }
    }
}

// ================= fused GAT edge-softmax + aggregate + pool + head =================
// warp per dst node: max scan, den scan, weighted z accumulation, dot(Wd), atomicAdd out.
__global__ void __launch_bounds__(256) k_gat_csr(const float* __restrict__ Wd,
                                                 const int* __restrict__ gids,
                                                 float* __restrict__ out) {
    int warp = (blockIdx.x * 256 + threadIdx.x) >> 5;
    int lane = threadIdx.x & 31;
    if (warp >= NN) return;
    int beg = __ldg(&g_rows[warp]), end = __ldg(&g_rows[warp + 1]);
    if (beg == end) return;
    float ern = __ldg(&g_er[warp]);

    // pass 1: max over edges (lane-parallel)
    float mx = -3.0e38f;
    for (int i = beg + lane; i < end; i += 32) {
        unsigned p = __ldg(&g_epack[i]);
        float ev = __ldg(&g_el[p & 0xffffu]) + ern;
        ev = ev > 0.f ? ev : NEG_SLOPE * ev;
        mx = fmaxf(mx, ev);
    }
    mx = fmaxf(mx, __shfl_xor_sync(0xffffffffu, mx, 16));
    mx = fmaxf(mx, __shfl_xor_sync(0xffffffffu, mx, 8));
    mx = fmaxf(mx, __shfl_xor_sync(0xffffffffu, mx, 4));
    mx = fmaxf(mx, __shfl_xor_sync(0xffffffffu, mx, 2));
    mx = fmaxf(mx, __shfl_xor_sync(0xffffffffu, mx, 1));

    // pass 2: denominator (lane-parallel)
    float den = 0.f;
    for (int i = beg + lane; i < end; i += 32) {
        unsigned p = __ldg(&g_epack[i]);
        float ev = __ldg(&g_el[p & 0xffffu]) + ern;
        ev = ev > 0.f ? ev : NEG_SLOPE * ev;
        den += __expf(ev - mx);
    }
    den += __shfl_xor_sync(0xffffffffu, den, 16);
    den += __shfl_xor_sync(0xffffffffu, den, 8);
    den += __shfl_xor_sync(0xffffffffu, den, 4);
    den += __shfl_xor_sync(0xffffffffu, den, 2);
    den += __shfl_xor_sync(0xffffffffu, den, 1);

    // pass 3: weighted accumulation (per edge, cols across lanes)
    float a0 = 0.f, a1 = 0.f;
    int i = beg;
    for (; i + 2 <= end; i += 2) {
        unsigned p0 = __ldg(&g_epack[i]);
        unsigned p1 = __ldg(&g_epack[i + 1]);
        unsigned s0 = p0 & 0xffffu, s1 = p1 & 0xffffu;
        float e0 = __ldg(&g_el[s0]) + ern; e0 = e0 > 0.f ? e0 : NEG_SLOPE * e0;
        float e1 = __ldg(&g_el[s1]) + ern; e1 = e1 > 0.f ? e1 : NEG_SLOPE * e1;
        const float* z0 = g_z + (size_t)s0 * DD + lane;
        const float* z1 = g_z + (size_t)s1 * DD + lane;
        float v00 = __ldg(z0), v01 = __ldg(z0 + 32);
        float v10 = __ldg(z1), v11 = __ldg(z1 + 32);
        float w0 = __expf(e0 - mx), w1 = __expf(e1 - mx);
        a0 = fmaf(w0, v00, a0); a1 = fmaf(w0, v01, a1);
        a0 = fmaf(w1, v10, a0); a1 = fmaf(w1, v11, a1);
    }
    for (; i < end; i++) {
        unsigned p = __ldg(&g_epack[i]);
        unsigned s = p & 0xffffu;
        float ev = __ldg(&g_el[s]) + ern; ev = ev > 0.f ? ev : NEG_SLOPE * ev;
        float w = __expf(ev - mx);
        const float* zr = g_z + (size_t)s * DD + lane;
        a0 = fmaf(w, __ldg(zr), a0); a1 = fmaf(w, __ldg(zr + 32), a1);
    }
    float inv = __fdividef(1.f, fmaxf(den, 1e-9f));
    float pv = (a0 * __ldg(Wd + lane) + a1 * __ldg(Wd + 32 + lane)) * inv;
    pv += __shfl_xor_sync(0xffffffffu, pv, 16);
    pv += __shfl_xor_sync(0xffffffffu, pv, 8);
    pv += __shfl_xor_sync(0xffffffffu, pv, 4);
    pv += __shfl_xor_sync(0xffffffffu, pv, 2);
    pv += __shfl_xor_sync(0xffffffffu, pv, 1);
    if (lane == 0) atomicAdd(out + __ldg(gids + warp), pv);
}

// ---------------- out init ----------------
__global__ void k_out_init(const float* __restrict__ bd, float* __restrict__ out) {
    int t = threadIdx.x;
    if (t < NB) out[t] = bd[0];
}

// ---------------- launcher ----------------
extern "C" void kernel_launch(void* const* d_in, const int* in_sizes, int n_in,
                              void* d_out, int out_size) {
    const float* h    = (const float*)d_in[0];
    const float* Wrel = (const float*)d_in[1];
    const float* Wloop= (const float*)d_in[2];
    const float* brel = (const float*)d_in[3];
    const float* Wg   = (const float*)d_in[4];
    const float* al   = (const float*)d_in[5];
    const float* ar   = (const float*)d_in[6];
    const float* Wd   = (const float*)d_in[7];
    const float* bd   = (const float*)d_in[8];
    const int*   src  = (const int*)d_in[9];
    const int*   dst  = (const int*)d_in[10];
    const int*   et   = (const int*)d_in[11];
    const int*   gids = (const int*)d_in[12];
    float* out = (float*)d_out;

    const int nf_smem = (XK * DD + DD + 128 * 33) * 4;       // 99072 B
    const int gz_smem = (DD * DD + 2 * DD + 128 * 33) * 4;   // 33792 B
    cudaFuncSetAttribute((const void*)k_nodeF, cudaFuncAttributeMaxDynamicSharedMemorySize, nf_smem);
    cudaFuncSetAttribute((const void*)k_gatz,  cudaFuncAttributeMaxDynamicSharedMemorySize, gz_smem);

    const int nblkF = (NN + 127) / 128;            // 391
    const int wblk  = (NN * 32 + 255) / 256;       // 6250 (warp-per-node kernels)
    const int eblk  = (NE + 255) / 256;            // 6250
    const int dblk  = (NN + 255) / 256;            // 196

    // CSR build (once per call)
    k_zero_deg<<<dblk, 256>>>();
    k_hist<<<eblk, 256>>>(dst);
    k_scan<<<1, 1024>>>();
    k_place<<<eblk, 256>>>(src, dst, et);

    for (int l = 0; l < LL; l++) {
        k_agg_csr<<<wblk, 256>>>(h, l);
        k_nodeF<<<nblkF, 256, nf_smem>>>(h, l, Wrel + l * RR * DD * DD,
                                         Wloop + l * DD * DD, brel + l * DD);
    }
    k_gatz<<<nblkF, 256, gz_smem>>>(h, Wg, al, ar);
    k_out_init<<<1, NB>>>(bd, out);
    k_gat_csr<<<wblk, 256>>>(Wd, gids, out);
}